// round 1
// baseline (speedup 1.0000x reference)
#include <cuda_runtime.h>

#define NN 100000
#define NE 1600000
#define D  128
#define DOUT 40

// Scratch (allocation-free rule: __device__ globals)
__device__ float g_bufA[(size_t)NN * D];   // t_s = (x@W)*dinv  (gather source)
__device__ float g_bufB[(size_t)NN * D];   // accumulator, init to t_s
__device__ float g_dinv[NN];               // deg -> rsqrt(deg)

// ---------------- degree / dinv ----------------
__global__ void k_deg_init() {
    int i = blockIdx.x * blockDim.x + threadIdx.x;
    if (i < NN) g_dinv[i] = 1.0f;          // self-loop
}
__global__ void k_deg_edges(const int* __restrict__ dst) {
    int i = blockIdx.x * blockDim.x + threadIdx.x;
    if (i < NE) atomicAdd(&g_dinv[dst[i]], 1.0f);
}
__global__ void k_dinv() {
    int i = blockIdx.x * blockDim.x + threadIdx.x;
    if (i < NN) g_dinv[i] = rsqrtf(g_dinv[i]);
}

// ---------------- GEMM (warp per row, W in smem) ----------------
// MODE 0: X = raw input x.        t = x @ W;            write t*dinv -> bufA,bufB
// MODE 1: input = g_bufB (agg1).  h = relu(dinv*agg+b); t = h @ W;  write t*dinv -> bufA,bufB
template <int MODE>
__global__ __launch_bounds__(256)
void k_gemm(const float* __restrict__ X, const float* __restrict__ W,
            const float* __restrict__ bias)
{
    extern __shared__ float Ws[];          // D*D floats
    const int tid = threadIdx.x;
    for (int i = tid; i < D * D / 4; i += blockDim.x)
        ((float4*)Ws)[i] = ((const float4*)W)[i];
    __syncthreads();

    const int lane = tid & 31, warp = tid >> 5;
    const int NW = blockDim.x >> 5;

    float4 brow = make_float4(0.f, 0.f, 0.f, 0.f);
    if (MODE == 1) brow = ((const float4*)bias)[lane];

    for (int row = blockIdx.x * NW + warp; row < NN; row += gridDim.x * NW) {
        const float di = g_dinv[row];
        float xr[4];
        if (MODE == 0) {
            float4 v = ((const float4*)(X + (size_t)row * D))[lane];
            xr[0] = v.x; xr[1] = v.y; xr[2] = v.z; xr[3] = v.w;
        } else {
            float4 a = ((const float4*)(g_bufB + (size_t)row * D))[lane];
            xr[0] = fmaxf(fmaf(di, a.x, brow.x), 0.f);
            xr[1] = fmaxf(fmaf(di, a.y, brow.y), 0.f);
            xr[2] = fmaxf(fmaf(di, a.z, brow.z), 0.f);
            xr[3] = fmaxf(fmaf(di, a.w, brow.w), 0.f);
        }
        float a0 = 0.f, a1 = 0.f, a2 = 0.f, a3 = 0.f;
#pragma unroll
        for (int k = 0; k < D; k++) {
            float xv = __shfl_sync(0xffffffffu, xr[k & 3], k >> 2);
            float4 w = ((const float4*)Ws)[k * 32 + lane];
            a0 = fmaf(xv, w.x, a0);
            a1 = fmaf(xv, w.y, a1);
            a2 = fmaf(xv, w.z, a2);
            a3 = fmaf(xv, w.w, a3);
        }
        float4 o = make_float4(a0 * di, a1 * di, a2 * di, a3 * di);
        ((float4*)(g_bufA + (size_t)row * D))[lane] = o;
        ((float4*)(g_bufB + (size_t)row * D))[lane] = o;
    }
}

// ---------------- edge aggregation: warp per edge ----------------
__global__ __launch_bounds__(256)
void k_edge(const int* __restrict__ src, const int* __restrict__ dst)
{
    unsigned w = (blockIdx.x * blockDim.x + threadIdx.x) >> 5;
    if (w >= NE) return;
    const int lane = threadIdx.x & 31;
    const int s = __ldg(src + w);
    const int d = __ldg(dst + w);
    float4 v = ((const float4*)(g_bufA + (size_t)s * D))[lane];
    float* p = g_bufB + (size_t)d * D + lane * 4;
    asm volatile("red.global.add.v4.f32 [%0], {%1,%2,%3,%4};"
                 :: "l"(p), "f"(v.x), "f"(v.y), "f"(v.z), "f"(v.w)
                 : "memory");
}

// ---------------- final: h2 = dinv*agg2 + b2; out = h2 @ Wout + bout ----------------
__global__ __launch_bounds__(256)
void k_out(const float* __restrict__ Wout, const float* __restrict__ b2,
           const float* __restrict__ bout, float* __restrict__ out)
{
    extern __shared__ float Ws[];          // D*DOUT floats
    const int tid = threadIdx.x;
    for (int i = tid; i < D * DOUT; i += blockDim.x)
        Ws[i] = Wout[i];
    __syncthreads();

    const int lane = tid & 31, warp = tid >> 5;
    const int NW = blockDim.x >> 5;

    float4 b2r = ((const float4*)b2)[lane];
    float bo0 = 0.f, bo1 = 0.f;
    if (lane < DOUT / 2) { bo0 = bout[2 * lane]; bo1 = bout[2 * lane + 1]; }

    for (int row = blockIdx.x * NW + warp; row < NN; row += gridDim.x * NW) {
        const float di = g_dinv[row];
        float4 a = ((const float4*)(g_bufB + (size_t)row * D))[lane];
        float xr[4];
        xr[0] = fmaf(di, a.x, b2r.x);
        xr[1] = fmaf(di, a.y, b2r.y);
        xr[2] = fmaf(di, a.z, b2r.z);
        xr[3] = fmaf(di, a.w, b2r.w);
        float a0 = 0.f, a1 = 0.f;
#pragma unroll
        for (int k = 0; k < D; k++) {
            float xv = __shfl_sync(0xffffffffu, xr[k & 3], k >> 2);
            if (lane < DOUT / 2) {
                float2 w = *(const float2*)(Ws + k * DOUT + 2 * lane);
                a0 = fmaf(xv, w.x, a0);
                a1 = fmaf(xv, w.y, a1);
            }
        }
        if (lane < DOUT / 2) {
            float2 o = make_float2(a0 + bo0, a1 + bo1);
            *(float2*)(out + (size_t)row * DOUT + 2 * lane) = o;
        }
    }
}

extern "C" void kernel_launch(void* const* d_in, const int* in_sizes, int n_in,
                              void* d_out, int out_size)
{
    const float* x    = (const float*)d_in[0];
    const int*   ei   = (const int*)  d_in[1];
    const float* W1   = (const float*)d_in[2];
    const float* b1   = (const float*)d_in[3];
    const float* W2   = (const float*)d_in[4];
    const float* b2   = (const float*)d_in[5];
    const float* Wout = (const float*)d_in[6];
    const float* bout = (const float*)d_in[7];
    const int* src = ei;
    const int* dst = ei + NE;
    float* out = (float*)d_out;

    cudaFuncSetAttribute(k_gemm<0>, cudaFuncAttributeMaxDynamicSharedMemorySize, D * D * 4);
    cudaFuncSetAttribute(k_gemm<1>, cudaFuncAttributeMaxDynamicSharedMemorySize, D * D * 4);

    const int GEMM_GRID = 1480;       // persistent-ish, W loaded once per block
    const int SMEM_GEMM = D * D * 4;  // 64 KB
    const int SMEM_OUT  = D * DOUT * 4;

    k_deg_init<<<(NN + 255) / 256, 256>>>();
    k_deg_edges<<<(NE + 255) / 256, 256>>>(dst);
    k_dinv<<<(NN + 255) / 256, 256>>>();

    // layer 1
    k_gemm<0><<<GEMM_GRID, 256, SMEM_GEMM>>>(x, W1, nullptr);
    k_edge<<<(NE + 7) / 8, 256>>>(src, dst);

    // layer 2 (fuses layer-1 epilogue: relu(dinv*agg + b1))
    k_gemm<1><<<GEMM_GRID, 256, SMEM_GEMM>>>(nullptr, W2, b1);
    k_edge<<<(NE + 7) / 8, 256>>>(src, dst);

    // output layer (fuses layer-2 epilogue: dinv*agg + b2)
    k_out<<<GEMM_GRID, 256, SMEM_OUT>>>(Wout, b2, bout, out);
}

// round 3
// speedup vs baseline: 1.5310x; 1.5310x over previous
#include <cuda_runtime.h>

#define NN 100000
#define NE 1600000
#define D  128
#define DOUT 40
#define ROWS 8
#define NGROUP (NN / ROWS)   // 12500

// Scratch (allocation-free rule: __device__ globals)
__device__ float g_bufA[(size_t)NN * D];   // t_s = (x@W)*dinv  (gather source)
__device__ float g_bufB[(size_t)NN * D];   // accumulator, init to t_s
__device__ float g_dinv[NN];               // deg -> rsqrt(deg)

__device__ __forceinline__ unsigned long long ffma2(unsigned long long a,
                                                    unsigned long long b,
                                                    unsigned long long c) {
    unsigned long long d;
    asm("fma.rn.f32x2 %0, %1, %2, %3;" : "=l"(d) : "l"(a), "l"(b), "l"(c));
    return d;
}
__device__ __forceinline__ unsigned long long pack2(float lo, float hi) {
    unsigned long long d;
    asm("mov.b64 %0, {%1, %2};" : "=l"(d) : "f"(lo), "f"(hi));
    return d;
}
__device__ __forceinline__ float2 unpack2(unsigned long long v) {
    float2 r;
    asm("mov.b64 {%0, %1}, %2;" : "=f"(r.x), "=f"(r.y) : "l"(v));
    return r;
}

// ---------------- degree / dinv ----------------
__global__ void k_deg_init() {
    int i = blockIdx.x * blockDim.x + threadIdx.x;
    if (i < NN) g_dinv[i] = 1.0f;          // self-loop
}
__global__ void k_deg_edges(const int* __restrict__ dst) {
    int i = blockIdx.x * blockDim.x + threadIdx.x;
    if (i < NE) atomicAdd(&g_dinv[dst[i]], 1.0f);
}
__global__ void k_dinv() {
    int i = blockIdx.x * blockDim.x + threadIdx.x;
    if (i < NN) g_dinv[i] = rsqrtf(g_dinv[i]);
}

// ---------------- GEMM (8 rows per warp, FFMA2, W in smem) ----------------
// MODE 0: X = raw input x.        t = x @ W;            write t*dinv -> bufA,bufB
// MODE 1: input = g_bufB (agg1).  h = relu(dinv*agg+b); t = h @ W;  write t*dinv -> bufA,bufB
template <int MODE>
__global__ __launch_bounds__(256)
void k_gemm(const float* __restrict__ X, const float* __restrict__ W,
            const float* __restrict__ bias)
{
    extern __shared__ float Ws[];          // D*D floats
    const int tid = threadIdx.x;
    for (int i = tid; i < D * D / 4; i += blockDim.x)
        ((float4*)Ws)[i] = ((const float4*)W)[i];
    __syncthreads();

    const int lane = tid & 31, warp = tid >> 5;
    const int NW = blockDim.x >> 5;

    float4 brow = make_float4(0.f, 0.f, 0.f, 0.f);
    if (MODE == 1) brow = ((const float4*)bias)[lane];

    for (int g = blockIdx.x * NW + warp; g < NGROUP; g += gridDim.x * NW) {
        const int row0 = g * ROWS;
        float xr[ROWS][4];
        float di[ROWS];
#pragma unroll
        for (int r = 0; r < ROWS; r++) {
            const int row = row0 + r;
            di[r] = g_dinv[row];
            if (MODE == 0) {
                float4 v = ((const float4*)(X + (size_t)row * D))[lane];
                xr[r][0] = v.x; xr[r][1] = v.y; xr[r][2] = v.z; xr[r][3] = v.w;
            } else {
                float4 a = ((const float4*)(g_bufB + (size_t)row * D))[lane];
                xr[r][0] = fmaxf(fmaf(di[r], a.x, brow.x), 0.f);
                xr[r][1] = fmaxf(fmaf(di[r], a.y, brow.y), 0.f);
                xr[r][2] = fmaxf(fmaf(di[r], a.z, brow.z), 0.f);
                xr[r][3] = fmaxf(fmaf(di[r], a.w, brow.w), 0.f);
            }
        }

        unsigned long long acc0[ROWS], acc1[ROWS];
#pragma unroll
        for (int r = 0; r < ROWS; r++) { acc0[r] = 0ull; acc1[r] = 0ull; }

#pragma unroll 4
        for (int k = 0; k < D; k++) {
            ulonglong2 w = ((const ulonglong2*)Ws)[k * 32 + lane];
#pragma unroll
            for (int r = 0; r < ROWS; r++) {
                float xv = __shfl_sync(0xffffffffu, xr[r][k & 3], k >> 2);
                unsigned long long xvv = pack2(xv, xv);
                acc0[r] = ffma2(xvv, w.x, acc0[r]);
                acc1[r] = ffma2(xvv, w.y, acc1[r]);
            }
        }

#pragma unroll
        for (int r = 0; r < ROWS; r++) {
            const int row = row0 + r;
            float2 lo = unpack2(acc0[r]);
            float2 hi = unpack2(acc1[r]);
            float4 o = make_float4(lo.x * di[r], lo.y * di[r],
                                   hi.x * di[r], hi.y * di[r]);
            ((float4*)(g_bufA + (size_t)row * D))[lane] = o;
            ((float4*)(g_bufB + (size_t)row * D))[lane] = o;
        }
    }
}

// ---------------- edge aggregation: warp per edge ----------------
__global__ __launch_bounds__(256)
void k_edge(const int* __restrict__ src, const int* __restrict__ dst)
{
    unsigned w = (blockIdx.x * blockDim.x + threadIdx.x) >> 5;
    if (w >= NE) return;
    const int lane = threadIdx.x & 31;
    const int s = __ldg(src + w);
    const int d = __ldg(dst + w);
    float4 v = ((const float4*)(g_bufA + (size_t)s * D))[lane];
    float* p = g_bufB + (size_t)d * D + lane * 4;
    asm volatile("red.global.add.v4.f32 [%0], {%1,%2,%3,%4};"
                 :: "l"(p), "f"(v.x), "f"(v.y), "f"(v.z), "f"(v.w)
                 : "memory");
}

// ---------------- final: h2 = dinv*agg2 + b2; out = h2 @ Wout + bout ----------------
__global__ __launch_bounds__(256)
void k_out(const float* __restrict__ Wout, const float* __restrict__ b2,
           const float* __restrict__ bout, float* __restrict__ out)
{
    extern __shared__ float Ws[];          // D*DOUT floats
    const int tid = threadIdx.x;
    for (int i = tid; i < D * DOUT; i += blockDim.x)
        Ws[i] = Wout[i];
    __syncthreads();

    const int lane = tid & 31, warp = tid >> 5;
    const int NW = blockDim.x >> 5;
    const bool act = (lane < DOUT / 2);

    float4 b2r = ((const float4*)b2)[lane];
    float bo0 = 0.f, bo1 = 0.f;
    if (act) { bo0 = bout[2 * lane]; bo1 = bout[2 * lane + 1]; }

    for (int g = blockIdx.x * NW + warp; g < NGROUP; g += gridDim.x * NW) {
        const int row0 = g * ROWS;
        float xr[ROWS][4];
#pragma unroll
        for (int r = 0; r < ROWS; r++) {
            const int row = row0 + r;
            const float di = g_dinv[row];
            float4 a = ((const float4*)(g_bufB + (size_t)row * D))[lane];
            xr[r][0] = fmaf(di, a.x, b2r.x);
            xr[r][1] = fmaf(di, a.y, b2r.y);
            xr[r][2] = fmaf(di, a.z, b2r.z);
            xr[r][3] = fmaf(di, a.w, b2r.w);
        }

        unsigned long long acc[ROWS];
#pragma unroll
        for (int r = 0; r < ROWS; r++) acc[r] = 0ull;

#pragma unroll 4
        for (int k = 0; k < D; k++) {
            unsigned long long w = 0ull;
            if (act) w = *(const unsigned long long*)(Ws + k * DOUT + 2 * lane);
#pragma unroll
            for (int r = 0; r < ROWS; r++) {
                float xv = __shfl_sync(0xffffffffu, xr[r][k & 3], k >> 2);
                unsigned long long xvv = pack2(xv, xv);
                acc[r] = ffma2(xvv, w, acc[r]);
            }
        }

        if (act) {
#pragma unroll
            for (int r = 0; r < ROWS; r++) {
                float2 v = unpack2(acc[r]);
                float2 o = make_float2(v.x + bo0, v.y + bo1);
                *(float2*)(out + (size_t)(row0 + r) * DOUT + 2 * lane) = o;
            }
        }
    }
}

extern "C" void kernel_launch(void* const* d_in, const int* in_sizes, int n_in,
                              void* d_out, int out_size)
{
    const float* x    = (const float*)d_in[0];
    const int*   ei   = (const int*)  d_in[1];
    const float* W1   = (const float*)d_in[2];
    const float* b1   = (const float*)d_in[3];
    const float* W2   = (const float*)d_in[4];
    const float* b2   = (const float*)d_in[5];
    const float* Wout = (const float*)d_in[6];
    const float* bout = (const float*)d_in[7];
    const int* src = ei;
    const int* dst = ei + NE;
    float* out = (float*)d_out;

    cudaFuncSetAttribute(k_gemm<0>, cudaFuncAttributeMaxDynamicSharedMemorySize, D * D * 4);
    cudaFuncSetAttribute(k_gemm<1>, cudaFuncAttributeMaxDynamicSharedMemorySize, D * D * 4);

    const int GEMM_GRID = (NGROUP + 7) / 8;   // 1563: one 8-row group per warp
    const int SMEM_GEMM = D * D * 4;          // 64 KB
    const int SMEM_OUT  = D * DOUT * 4;

    k_deg_init<<<(NN + 255) / 256, 256>>>();
    k_deg_edges<<<(NE + 255) / 256, 256>>>(dst);
    k_dinv<<<(NN + 255) / 256, 256>>>();

    // layer 1
    k_gemm<0><<<GEMM_GRID, 256, SMEM_GEMM>>>(x, W1, nullptr);
    k_edge<<<(NE + 7) / 8, 256>>>(src, dst);

    // layer 2 (fuses layer-1 epilogue: relu(dinv*agg + b1))
    k_gemm<1><<<GEMM_GRID, 256, SMEM_GEMM>>>(nullptr, W2, b1);
    k_edge<<<(NE + 7) / 8, 256>>>(src, dst);

    // output layer (fuses layer-2 epilogue: dinv*agg + b2)
    k_out<<<GEMM_GRID, 256, SMEM_OUT>>>(Wout, b2, bout, out);
}

// round 4
// speedup vs baseline: 2.4800x; 1.6198x over previous
#include <cuda_runtime.h>

#define NN 100000
#define NE 1600000
#define D  128
#define DOUT 40
#define ROWS 8
#define NGROUP (NN / ROWS)   // 12500

#define SCAN_B 512
#define NSCANB ((NN + SCAN_B - 1) / SCAN_B)   // 196

// Scratch (allocation-free rule: __device__ globals)
__device__ float g_bufA[(size_t)NN * D];   // t_s = (x@W)*dinv  (gather source)
__device__ float g_bufB[(size_t)NN * D];   // aggregated result
__device__ float g_dinv[NN];
__device__ int   g_cnt[NN];                // in-degree (excl self)
__device__ int   g_rowptr[NN];             // CSR start
__device__ int   g_woff[NN];               // scatter running offsets
__device__ int   g_srcs[NE];               // src ids grouped by dst
__device__ int   g_bsum[NSCANB];           // block totals
__device__ int   g_boff[NSCANB];           // exclusive block offsets

__device__ __forceinline__ unsigned long long ffma2(unsigned long long a,
                                                    unsigned long long b,
                                                    unsigned long long c) {
    unsigned long long d;
    asm("fma.rn.f32x2 %0, %1, %2, %3;" : "=l"(d) : "l"(a), "l"(b), "l"(c));
    return d;
}
__device__ __forceinline__ unsigned long long pack2(float lo, float hi) {
    unsigned long long d;
    asm("mov.b64 %0, {%1, %2};" : "=l"(d) : "f"(lo), "f"(hi));
    return d;
}
__device__ __forceinline__ float2 unpack2(unsigned long long v) {
    float2 r;
    asm("mov.b64 {%0, %1}, %2;" : "=f"(r.x), "=f"(r.y) : "l"(v));
    return r;
}

// ---------------- CSR build ----------------
__global__ void k_zero() {
    int i = blockIdx.x * blockDim.x + threadIdx.x;
    if (i < NN) g_cnt[i] = 0;
}
__global__ void k_hist(const int* __restrict__ dst) {
    int i = blockIdx.x * blockDim.x + threadIdx.x;
    if (i < NE) atomicAdd(&g_cnt[dst[i]], 1);
}
// per-block exclusive scan of counts; emit block totals
__global__ __launch_bounds__(SCAN_B)
void k_scan1() {
    __shared__ int sh[SCAN_B];
    int i = blockIdx.x * SCAN_B + threadIdx.x;
    int v = (i < NN) ? g_cnt[i] : 0;
    sh[threadIdx.x] = v;
    __syncthreads();
    int acc = v;
#pragma unroll
    for (int off = 1; off < SCAN_B; off <<= 1) {
        int t = (threadIdx.x >= off) ? sh[threadIdx.x - off] : 0;
        __syncthreads();
        acc += t;
        sh[threadIdx.x] = acc;
        __syncthreads();
    }
    if (i < NN) g_rowptr[i] = acc - v;          // exclusive within block
    if (threadIdx.x == SCAN_B - 1) g_bsum[blockIdx.x] = acc;
}
__global__ void k_scan2() {
    if (threadIdx.x == 0) {
        int run = 0;
        for (int b = 0; b < NSCANB; b++) { g_boff[b] = run; run += g_bsum[b]; }
    }
}
__global__ void k_finalize() {
    int i = blockIdx.x * blockDim.x + threadIdx.x;
    if (i < NN) {
        int p = g_rowptr[i] + g_boff[i / SCAN_B];
        g_rowptr[i] = p;
        g_woff[i]   = p;
        g_dinv[i]   = rsqrtf((float)(g_cnt[i] + 1));
    }
}
__global__ void k_scatter(const int* __restrict__ src, const int* __restrict__ dst) {
    int i = blockIdx.x * blockDim.x + threadIdx.x;
    if (i < NE) {
        int pos = atomicAdd(&g_woff[dst[i]], 1);
        g_srcs[pos] = src[i];
    }
}

// ---------------- GEMM (8 rows per warp, FFMA2, W in smem) ----------------
// MODE 0: X = raw input x.        t = x @ W;            write t*dinv -> bufA
// MODE 1: input = g_bufB (agg).   h = relu(dinv*agg+b); t = h @ W;  write t*dinv -> bufA
template <int MODE>
__global__ __launch_bounds__(256)
void k_gemm(const float* __restrict__ X, const float* __restrict__ W,
            const float* __restrict__ bias)
{
    extern __shared__ float Ws[];          // D*D floats
    const int tid = threadIdx.x;
    for (int i = tid; i < D * D / 4; i += blockDim.x)
        ((float4*)Ws)[i] = ((const float4*)W)[i];
    __syncthreads();

    const int lane = tid & 31, warp = tid >> 5;
    const int NW = blockDim.x >> 5;

    float4 brow = make_float4(0.f, 0.f, 0.f, 0.f);
    if (MODE == 1) brow = ((const float4*)bias)[lane];

    for (int g = blockIdx.x * NW + warp; g < NGROUP; g += gridDim.x * NW) {
        const int row0 = g * ROWS;
        float xr[ROWS][4];
        float di[ROWS];
#pragma unroll
        for (int r = 0; r < ROWS; r++) {
            const int row = row0 + r;
            di[r] = g_dinv[row];
            if (MODE == 0) {
                float4 v = ((const float4*)(X + (size_t)row * D))[lane];
                xr[r][0] = v.x; xr[r][1] = v.y; xr[r][2] = v.z; xr[r][3] = v.w;
            } else {
                float4 a = ((const float4*)(g_bufB + (size_t)row * D))[lane];
                xr[r][0] = fmaxf(fmaf(di[r], a.x, brow.x), 0.f);
                xr[r][1] = fmaxf(fmaf(di[r], a.y, brow.y), 0.f);
                xr[r][2] = fmaxf(fmaf(di[r], a.z, brow.z), 0.f);
                xr[r][3] = fmaxf(fmaf(di[r], a.w, brow.w), 0.f);
            }
        }

        unsigned long long acc0[ROWS], acc1[ROWS];
#pragma unroll
        for (int r = 0; r < ROWS; r++) { acc0[r] = 0ull; acc1[r] = 0ull; }

#pragma unroll 4
        for (int k = 0; k < D; k++) {
            ulonglong2 w = ((const ulonglong2*)Ws)[k * 32 + lane];
#pragma unroll
            for (int r = 0; r < ROWS; r++) {
                float xv = __shfl_sync(0xffffffffu, xr[r][k & 3], k >> 2);
                unsigned long long xvv = pack2(xv, xv);
                acc0[r] = ffma2(xvv, w.x, acc0[r]);
                acc1[r] = ffma2(xvv, w.y, acc1[r]);
            }
        }

#pragma unroll
        for (int r = 0; r < ROWS; r++) {
            const int row = row0 + r;
            float2 lo = unpack2(acc0[r]);
            float2 hi = unpack2(acc1[r]);
            float4 o = make_float4(lo.x * di[r], lo.y * di[r],
                                   hi.x * di[r], hi.y * di[r]);
            ((float4*)(g_bufA + (size_t)row * D))[lane] = o;
        }
    }
}

// ---------------- CSR gather aggregation: warp per node ----------------
__global__ __launch_bounds__(256)
void k_gather()
{
    const int v = (blockIdx.x * blockDim.x + threadIdx.x) >> 5;
    if (v >= NN) return;
    const int lane = threadIdx.x & 31;
    const int start = g_rowptr[v];
    const int deg   = g_cnt[v];

    float4 acc = ((const float4*)(g_bufA + (size_t)v * D))[lane];  // self loop

    int j = 0;
    for (; j + 4 <= deg; j += 4) {
        int s0 = __ldg(g_srcs + start + j + 0);
        int s1 = __ldg(g_srcs + start + j + 1);
        int s2 = __ldg(g_srcs + start + j + 2);
        int s3 = __ldg(g_srcs + start + j + 3);
        float4 v0 = ((const float4*)(g_bufA + (size_t)s0 * D))[lane];
        float4 v1 = ((const float4*)(g_bufA + (size_t)s1 * D))[lane];
        float4 v2 = ((const float4*)(g_bufA + (size_t)s2 * D))[lane];
        float4 v3 = ((const float4*)(g_bufA + (size_t)s3 * D))[lane];
        acc.x += v0.x + v1.x + v2.x + v3.x;
        acc.y += v0.y + v1.y + v2.y + v3.y;
        acc.z += v0.z + v1.z + v2.z + v3.z;
        acc.w += v0.w + v1.w + v2.w + v3.w;
    }
    for (; j < deg; j++) {
        int s = __ldg(g_srcs + start + j);
        float4 u = ((const float4*)(g_bufA + (size_t)s * D))[lane];
        acc.x += u.x; acc.y += u.y; acc.z += u.z; acc.w += u.w;
    }
    ((float4*)(g_bufB + (size_t)v * D))[lane] = acc;
}

// ---------------- final: h2 = dinv*agg2 + b2; out = h2 @ Wout + bout ----------------
__global__ __launch_bounds__(256)
void k_out(const float* __restrict__ Wout, const float* __restrict__ b2,
           const float* __restrict__ bout, float* __restrict__ out)
{
    extern __shared__ float Ws[];          // D*DOUT floats
    const int tid = threadIdx.x;
    for (int i = tid; i < D * DOUT; i += blockDim.x)
        Ws[i] = Wout[i];
    __syncthreads();

    const int lane = tid & 31, warp = tid >> 5;
    const int NW = blockDim.x >> 5;
    const bool act = (lane < DOUT / 2);

    float4 b2r = ((const float4*)b2)[lane];
    float bo0 = 0.f, bo1 = 0.f;
    if (act) { bo0 = bout[2 * lane]; bo1 = bout[2 * lane + 1]; }

    for (int g = blockIdx.x * NW + warp; g < NGROUP; g += gridDim.x * NW) {
        const int row0 = g * ROWS;
        float xr[ROWS][4];
#pragma unroll
        for (int r = 0; r < ROWS; r++) {
            const int row = row0 + r;
            const float di = g_dinv[row];
            float4 a = ((const float4*)(g_bufB + (size_t)row * D))[lane];
            xr[r][0] = fmaf(di, a.x, b2r.x);
            xr[r][1] = fmaf(di, a.y, b2r.y);
            xr[r][2] = fmaf(di, a.z, b2r.z);
            xr[r][3] = fmaf(di, a.w, b2r.w);
        }

        unsigned long long acc[ROWS];
#pragma unroll
        for (int r = 0; r < ROWS; r++) acc[r] = 0ull;

#pragma unroll 4
        for (int k = 0; k < D; k++) {
            unsigned long long w = 0ull;
            if (act) w = *(const unsigned long long*)(Ws + k * DOUT + 2 * lane);
#pragma unroll
            for (int r = 0; r < ROWS; r++) {
                float xv = __shfl_sync(0xffffffffu, xr[r][k & 3], k >> 2);
                unsigned long long xvv = pack2(xv, xv);
                acc[r] = ffma2(xvv, w, acc[r]);
            }
        }

        if (act) {
#pragma unroll
            for (int r = 0; r < ROWS; r++) {
                float2 v = unpack2(acc[r]);
                float2 o = make_float2(v.x + bo0, v.y + bo1);
                *(float2*)(out + (size_t)(row0 + r) * DOUT + 2 * lane) = o;
            }
        }
    }
}

extern "C" void kernel_launch(void* const* d_in, const int* in_sizes, int n_in,
                              void* d_out, int out_size)
{
    const float* x    = (const float*)d_in[0];
    const int*   ei   = (const int*)  d_in[1];
    const float* W1   = (const float*)d_in[2];
    const float* b1   = (const float*)d_in[3];
    const float* W2   = (const float*)d_in[4];
    const float* b2   = (const float*)d_in[5];
    const float* Wout = (const float*)d_in[6];
    const float* bout = (const float*)d_in[7];
    const int* src = ei;
    const int* dst = ei + NE;
    float* out = (float*)d_out;

    cudaFuncSetAttribute(k_gemm<0>, cudaFuncAttributeMaxDynamicSharedMemorySize, D * D * 4);
    cudaFuncSetAttribute(k_gemm<1>, cudaFuncAttributeMaxDynamicSharedMemorySize, D * D * 4);

    const int GEMM_GRID = (NGROUP + 7) / 8;   // one 8-row group per warp
    const int SMEM_GEMM = D * D * 4;          // 64 KB
    const int SMEM_OUT  = D * DOUT * 4;
    const int GATHER_GRID = (NN * 32 + 255) / 256;   // warp per node

    // ---- CSR build (also yields degrees -> dinv) ----
    k_zero<<<(NN + 255) / 256, 256>>>();
    k_hist<<<(NE + 255) / 256, 256>>>(dst);
    k_scan1<<<NSCANB, SCAN_B>>>();
    k_scan2<<<1, 32>>>();
    k_finalize<<<(NN + 255) / 256, 256>>>();
    k_scatter<<<(NE + 255) / 256, 256>>>(src, dst);

    // ---- layer 1 ----
    k_gemm<0><<<GEMM_GRID, 256, SMEM_GEMM>>>(x, W1, nullptr);
    k_gather<<<GATHER_GRID, 256>>>();

    // ---- layer 2 (fuses layer-1 epilogue: relu(dinv*agg + b1)) ----
    k_gemm<1><<<GEMM_GRID, 256, SMEM_GEMM>>>(nullptr, W2, b1);
    k_gather<<<GATHER_GRID, 256>>>();

    // ---- output layer (fuses layer-2 epilogue: dinv*agg + b2) ----
    k_out<<<GEMM_GRID, 256, SMEM_OUT>>>(Wout, b2, bout, out);
}